// round 11
// baseline (speedup 1.0000x reference)
#include <cuda_runtime.h>
#include <cuda_fp16.h>
#include <cstdint>

// UnionLayer via Taylor expansion -> fp16 tensor-core GEMM (mma.sync, generic PTX).
//   -log(1-t) = sum_{n=1..7} t^n / n,  t = u*w in [0, 0.5)
//   S[b,nh]   = sum_d sum_n u^n * (w^n / n)  == GEMM, K = 7*512
//   con: u = 1-x, y = 1/(1+S);  dis: u = x, y = 1 - 1/(1+S)
// R11 = R10's term-level software-pipelined mainloop (chain(n+1) before mma(n),
// double-buffered fragments) x 512-thread CTA split-K4:
//   warp w: m-slice (w&3)*32, d-quarter (w>>2)*128 (8 units of 16 d)
//   -> 4 warps/SMSP (occ ~24%), inner loop fits 128-reg cap (R10 measured 118).
// 48KB smem reduction merges quarters; epilogue fused in quarter-0 warps.
// Grid (8, 8, 2) = 128 CTAs, 1 per SM.

#define DDIM    512
#define NOUT    512
#define NCOLS   256
#define NTERMS  7
#define MTILE   128
#define NTILE   32
#define THREADS 512
#define RED_BYTES (3 * 4 * 32 * 32 * 4)   // 49152

__device__ __forceinline__ void mma16816(float* c, uint32_t a0, uint32_t a1,
                                         uint32_t a2, uint32_t a3,
                                         uint32_t b0, uint32_t b1) {
    asm volatile(
        "mma.sync.aligned.m16n8k16.row.col.f32.f16.f16.f32 "
        "{%0,%1,%2,%3}, {%4,%5,%6,%7}, {%8,%9}, {%0,%1,%2,%3};"
        : "+f"(c[0]), "+f"(c[1]), "+f"(c[2]), "+f"(c[3])
        : "r"(a0), "r"(a1), "r"(a2), "r"(a3), "r"(b0), "r"(b1));
}

__device__ __forceinline__ uint32_t h2u(__half2 h) {
    return *reinterpret_cast<uint32_t*>(&h);
}

__global__ __launch_bounds__(THREADS) void union_mma_kernel(
    const float* __restrict__ x,
    const float* __restrict__ Wcon,
    const float* __restrict__ Wdis,
    float* __restrict__ out)
{
    extern __shared__ float red[];   // [3][4][32*32]: partials from d-quarters 1..3

    const int tid  = threadIdx.x;
    const int wid  = tid >> 5;
    const int lane = tid & 31;
    const int g    = lane >> 2;        // 0..7
    const int t4   = lane & 3;         // 0..3
    const int msl  = wid & 3;          // m-slice (32 rows)
    const int dq   = wid >> 2;         // d-quarter 0..3
    const int bn0  = blockIdx.x * NTILE;
    const int bm0  = blockIdx.y * MTILE;
    const int z    = blockIdx.z;       // 0 = con, 1 = dis
    const float* __restrict__ W = z ? Wdis : Wcon;

    const float* __restrict__ pA = &x[(bm0 + msl * 32 + g) * DDIM + dq * 128 + 2 * t4];
    const float* __restrict__ pB = &W[(bn0 + g) * DDIM + dq * 128 + 2 * t4];

    float acc[2][4][4];
#pragma unroll
    for (int mt = 0; mt < 2; mt++)
#pragma unroll
        for (int nt = 0; nt < 4; nt++)
#pragma unroll
            for (int c = 0; c < 4; c++) acc[mt][nt][c] = 0.0f;

    const float kf[NTERMS] = {0.f, 0.5f, 2.f/3.f, 0.75f, 0.8f, 5.f/6.f, 6.f/7.f};
    const int stag = msl * 2;          // per-warp unit-order stagger (8 units)

    // staged raw for one 16-d unit: [row][pair]
    float2 sA[4][2], sB[4][2];
    {
        int off = ((0 + stag) & 7) * 16;
#pragma unroll
        for (int r = 0; r < 4; r++)
#pragma unroll
            for (int p = 0; p < 2; p++) {
                sA[r][p] = *reinterpret_cast<const float2*>(pA + r * 8 * DDIM + off + p * 8);
                sB[r][p] = *reinterpret_cast<const float2*>(pB + r * 8 * DDIM + off + p * 8);
            }
    }

#pragma unroll 1
    for (int u = 0; u < 8; u++) {
        // ---- build bases + term-1 fragments (buffer 0) ----
        __half2 baseA[4][2], baseB[4][2], curA[2][4][2], curB[2][4][2];
#pragma unroll
        for (int r = 0; r < 4; r++)
#pragma unroll
            for (int p = 0; p < 2; p++) {
                float ux = sA[r][p].x, uy = sA[r][p].y;
                if (z == 0) { ux = 1.0f - ux; uy = 1.0f - uy; }
                baseA[r][p]   = __floats2half2_rn(ux, uy);
                baseB[r][p]   = __floats2half2_rn(sB[r][p].x, sB[r][p].y);
                curA[0][r][p] = baseA[r][p];
                curB[0][r][p] = baseB[r][p];
            }

        // ---- prefetch next unit's raw ----
        if (u + 1 < 8) {
            int off = ((u + 1 + stag) & 7) * 16;
#pragma unroll
            for (int r = 0; r < 4; r++)
#pragma unroll
                for (int p = 0; p < 2; p++) {
                    sA[r][p] = *reinterpret_cast<const float2*>(pA + r * 8 * DDIM + off + p * 8);
                    sB[r][p] = *reinterpret_cast<const float2*>(pB + r * 8 * DDIM + off + p * 8);
                }
        }

        // ---- 7 terms, software-pipelined: chain(n+1) issued BEFORE mma(n) ----
#pragma unroll
        for (int n = 0; n < NTERMS; n++) {
            const int cb = n & 1, nb = (n + 1) & 1;
            if (n + 1 < NTERMS) {
                const __half2 kfh = __float2half2_rn(kf[n + 1]);
#pragma unroll
                for (int r = 0; r < 4; r++)
#pragma unroll
                    for (int p = 0; p < 2; p++) {
                        curA[nb][r][p] = __hmul2(curA[cb][r][p], baseA[r][p]);
                        __half2 bb     = __hmul2(baseB[r][p], kfh);     // independent
                        curB[nb][r][p] = __hmul2(curB[cb][r][p], bb);   // 1 dependent link
                    }
            }
#pragma unroll
            for (int mt = 0; mt < 2; mt++) {
                uint32_t a0 = h2u(curA[cb][mt * 2 + 0][0]);
                uint32_t a1 = h2u(curA[cb][mt * 2 + 1][0]);
                uint32_t a2 = h2u(curA[cb][mt * 2 + 0][1]);
                uint32_t a3 = h2u(curA[cb][mt * 2 + 1][1]);
#pragma unroll
                for (int nt = 0; nt < 4; nt++) {
                    mma16816(acc[mt][nt], a0, a1, a2, a3,
                             h2u(curB[cb][nt][0]), h2u(curB[cb][nt][1]));
                }
            }
        }
    }

    // ---- merge d-quarters: q1..q3 store partials, q0 adds + epilogue ----
    if (dq != 0) {
        float* tile = &red[((dq - 1) * 4 + msl) * 1024];
#pragma unroll
        for (int mt = 0; mt < 2; mt++)
#pragma unroll
            for (int hh = 0; hh < 2; hh++) {
                int r = mt * 16 + hh * 8 + g;
#pragma unroll
                for (int nt = 0; nt < 4; nt++) {
                    *reinterpret_cast<float2*>(&tile[r * 32 + nt * 8 + 2 * t4]) =
                        make_float2(acc[mt][nt][hh * 2 + 0], acc[mt][nt][hh * 2 + 1]);
                }
            }
    }
    __syncthreads();

    if (dq == 0) {
#pragma unroll
        for (int mt = 0; mt < 2; mt++) {
#pragma unroll
            for (int hh = 0; hh < 2; hh++) {
                int r = mt * 16 + hh * 8 + g;
                int m = bm0 + msl * 32 + r;
#pragma unroll
                for (int nt = 0; nt < 4; nt++) {
                    float S0 = acc[mt][nt][hh * 2 + 0];
                    float S1 = acc[mt][nt][hh * 2 + 1];
#pragma unroll
                    for (int q = 0; q < 3; q++) {
                        float2 o = *reinterpret_cast<const float2*>(
                            &red[(q * 4 + msl) * 1024 + r * 32 + nt * 8 + 2 * t4]);
                        S0 += o.x;
                        S1 += o.y;
                    }
                    float y0 = 1.0f / (1.0f + S0);
                    float y1 = 1.0f / (1.0f + S1);
                    if (z) { y0 = 1.0f - y0; y1 = 1.0f - y1; }
                    int col = bn0 + nt * 8 + 2 * t4;
                    *reinterpret_cast<float2*>(&out[m * NOUT + z * NCOLS + col]) =
                        make_float2(y0, y1);
                }
            }
        }
    }
}

extern "C" void kernel_launch(void* const* d_in, const int* in_sizes, int n_in,
                              void* d_out, int out_size)
{
    const float* x    = (const float*)d_in[0];
    const float* Wcon = (const float*)d_in[1];
    const float* Wdis = (const float*)d_in[2];
    float* out = (float*)d_out;

    cudaFuncSetAttribute(union_mma_kernel,
                         cudaFuncAttributeMaxDynamicSharedMemorySize, RED_BYTES);

    dim3 grid(NCOLS / NTILE, 1024 / MTILE, 2);   // (8, 8, 2) = 128 CTAs
    union_mma_kernel<<<grid, THREADS, RED_BYTES>>>(x, Wcon, Wdis, out);
}

// round 12
// speedup vs baseline: 1.0408x; 1.0408x over previous
#include <cuda_runtime.h>
#include <cuda_fp16.h>
#include <cstdint>

// UnionLayer via Taylor expansion -> fp16 tensor-core GEMM (mma.sync, generic PTX).
//   -log(1-t) = sum_{n=1..6} t^n / n,  t = u*w in [0, 0.5)   (tail bias ~0.03 on S~73)
//   S[b,nh]   = sum_d sum_n u^n * (w^n / n)  == GEMM, K = 6*512
//   con: u = 1-x, y = 1/(1+S);  dis: u = x, y = 1 - 1/(1+S)
// R12 = R10 (term-level software-pipelined register-fragment mainloop, 256 thr,
// 8 warps: 4 m-slices x 2 d-halves) with pure work removal:
//   (a) prep kernel pre-converts inputs to fp16 (u_con, u_dis, W_con, W_dis)
//       into __device__ scratch -> mainloop loses all FADD/F2FP, LDG bytes halve
//   (b) 6 Taylor terms instead of 7 (-14% HMMA + chains)
// Grid (8, 8, 2) = 128 CTAs, 1 per SM.

#define DDIM    512
#define NOUT    512
#define NCOLS   256
#define NTERMS  6
#define MTILE   128
#define NTILE   32
#define THREADS 256

// fp16 scratch: [z][row][d]
__device__ __half Ua[2][1024 * DDIM];      // z=0: 1-x, z=1: x      (2 MB)
__device__ __half Wb[2][NCOLS * DDIM];     // z=0: W_con, z=1: W_dis (0.5 MB)

__global__ __launch_bounds__(256) void prep_kernel(
    const float* __restrict__ x,
    const float* __restrict__ Wcon,
    const float* __restrict__ Wdis)
{
    const int t = blockIdx.x * blockDim.x + threadIdx.x;
    // x: threads [0, 65536): 8 floats each -> Ua[0], Ua[1]
    if (t < 65536) {
        const int base = t * 8;
        float4 v0 = *reinterpret_cast<const float4*>(&x[base]);
        float4 v1 = *reinterpret_cast<const float4*>(&x[base + 4]);
        __half2 con[4], dis[4];
        con[0] = __floats2half2_rn(1.0f - v0.x, 1.0f - v0.y);
        con[1] = __floats2half2_rn(1.0f - v0.z, 1.0f - v0.w);
        con[2] = __floats2half2_rn(1.0f - v1.x, 1.0f - v1.y);
        con[3] = __floats2half2_rn(1.0f - v1.z, 1.0f - v1.w);
        dis[0] = __floats2half2_rn(v0.x, v0.y);
        dis[1] = __floats2half2_rn(v0.z, v0.w);
        dis[2] = __floats2half2_rn(v1.x, v1.y);
        dis[3] = __floats2half2_rn(v1.z, v1.w);
        *reinterpret_cast<uint4*>(&Ua[0][base]) = *reinterpret_cast<const uint4*>(con);
        *reinterpret_cast<uint4*>(&Ua[1][base]) = *reinterpret_cast<const uint4*>(dis);
    } else if (t < 65536 + 32768) {
        const int i = t - 65536;          // 0..32767
        const int zz = i >> 14;           // 0: con, 1: dis
        const int base = (i & 16383) * 8;
        const float* src = zz ? Wdis : Wcon;
        float4 v0 = *reinterpret_cast<const float4*>(&src[base]);
        float4 v1 = *reinterpret_cast<const float4*>(&src[base + 4]);
        __half2 w[4];
        w[0] = __floats2half2_rn(v0.x, v0.y);
        w[1] = __floats2half2_rn(v0.z, v0.w);
        w[2] = __floats2half2_rn(v1.x, v1.y);
        w[3] = __floats2half2_rn(v1.z, v1.w);
        *reinterpret_cast<uint4*>(&Wb[zz][base]) = *reinterpret_cast<const uint4*>(w);
    }
}

__device__ __forceinline__ void mma16816(float* c, uint32_t a0, uint32_t a1,
                                         uint32_t a2, uint32_t a3,
                                         uint32_t b0, uint32_t b1) {
    asm volatile(
        "mma.sync.aligned.m16n8k16.row.col.f32.f16.f16.f32 "
        "{%0,%1,%2,%3}, {%4,%5,%6,%7}, {%8,%9}, {%0,%1,%2,%3};"
        : "+f"(c[0]), "+f"(c[1]), "+f"(c[2]), "+f"(c[3])
        : "r"(a0), "r"(a1), "r"(a2), "r"(a3), "r"(b0), "r"(b1));
}

__device__ __forceinline__ uint32_t h2u(__half2 h) {
    return *reinterpret_cast<uint32_t*>(&h);
}
__device__ __forceinline__ __half2 u2h(uint32_t u) {
    return *reinterpret_cast<__half2*>(&u);
}

__global__ __launch_bounds__(THREADS) void union_mma_kernel(
    float* __restrict__ out)
{
    __shared__ float red[4][32][32];   // d-half-1 partials (16 KB)

    const int tid  = threadIdx.x;
    const int wid  = tid >> 5;
    const int lane = tid & 31;
    const int g    = lane >> 2;        // 0..7
    const int t4   = lane & 3;         // 0..3
    const int msl  = wid & 3;          // m-slice (32 rows)
    const int dh   = wid >> 2;         // d-half 0/1
    const int bn0  = blockIdx.x * NTILE;
    const int bm0  = blockIdx.y * MTILE;
    const int z    = blockIdx.z;       // 0 = con, 1 = dis

    const __half* __restrict__ pA = &Ua[z][(bm0 + msl * 32 + g) * DDIM + dh * 256 + 2 * t4];
    const __half* __restrict__ pB = &Wb[z][(bn0 + g) * DDIM + dh * 256 + 2 * t4];

    float acc[2][4][4];
#pragma unroll
    for (int mt = 0; mt < 2; mt++)
#pragma unroll
        for (int nt = 0; nt < 4; nt++)
#pragma unroll
            for (int c = 0; c < 4; c++) acc[mt][nt][c] = 0.0f;

    const float kf[NTERMS] = {0.f, 0.5f, 2.f/3.f, 0.75f, 0.8f, 5.f/6.f};
    const int stag = msl * 4;          // per-warp unit-order stagger (16 units)

    // staged raw fp16 loads for one 16-d unit: [row][pair], LDG.32 each
    uint32_t sA[4][2], sB[4][2];
    {
        int off = ((0 + stag) & 15) * 16;
#pragma unroll
        for (int r = 0; r < 4; r++)
#pragma unroll
            for (int p = 0; p < 2; p++) {
                sA[r][p] = *reinterpret_cast<const uint32_t*>(pA + r * 8 * DDIM + off + p * 8);
                sB[r][p] = *reinterpret_cast<const uint32_t*>(pB + r * 8 * DDIM + off + p * 8);
            }
    }

#pragma unroll 1
    for (int u = 0; u < 16; u++) {
        // ---- bases are the staged halfs; term-1 fragments = bases ----
        __half2 baseA[4][2], baseB[4][2], curA[2][4][2], curB[2][4][2];
#pragma unroll
        for (int r = 0; r < 4; r++)
#pragma unroll
            for (int p = 0; p < 2; p++) {
                baseA[r][p]   = u2h(sA[r][p]);
                baseB[r][p]   = u2h(sB[r][p]);
                curA[0][r][p] = baseA[r][p];
                curB[0][r][p] = baseB[r][p];
            }

        // ---- prefetch next unit (consumed next iteration) ----
        if (u + 1 < 16) {
            int off = ((u + 1 + stag) & 15) * 16;
#pragma unroll
            for (int r = 0; r < 4; r++)
#pragma unroll
                for (int p = 0; p < 2; p++) {
                    sA[r][p] = *reinterpret_cast<const uint32_t*>(pA + r * 8 * DDIM + off + p * 8);
                    sB[r][p] = *reinterpret_cast<const uint32_t*>(pB + r * 8 * DDIM + off + p * 8);
                }
        }

        // ---- 6 terms, software-pipelined: chain(n+1) issued BEFORE mma(n) ----
#pragma unroll
        for (int n = 0; n < NTERMS; n++) {
            const int cb = n & 1, nb = (n + 1) & 1;
            if (n + 1 < NTERMS) {
                const __half2 kfh = __float2half2_rn(kf[n + 1]);
#pragma unroll
                for (int r = 0; r < 4; r++)
#pragma unroll
                    for (int p = 0; p < 2; p++) {
                        curA[nb][r][p] = __hmul2(curA[cb][r][p], baseA[r][p]);
                        __half2 bb     = __hmul2(baseB[r][p], kfh);     // independent
                        curB[nb][r][p] = __hmul2(curB[cb][r][p], bb);   // 1 dependent link
                    }
            }
#pragma unroll
            for (int mt = 0; mt < 2; mt++) {
                uint32_t a0 = h2u(curA[cb][mt * 2 + 0][0]);
                uint32_t a1 = h2u(curA[cb][mt * 2 + 1][0]);
                uint32_t a2 = h2u(curA[cb][mt * 2 + 0][1]);
                uint32_t a3 = h2u(curA[cb][mt * 2 + 1][1]);
#pragma unroll
                for (int nt = 0; nt < 4; nt++) {
                    mma16816(acc[mt][nt], a0, a1, a2, a3,
                             h2u(curB[cb][nt][0]), h2u(curB[cb][nt][1]));
                }
            }
        }
    }

    // ---- merge d-halves: half 1 stores, half 0 adds + epilogue ----
    if (dh == 1) {
#pragma unroll
        for (int mt = 0; mt < 2; mt++)
#pragma unroll
            for (int hh = 0; hh < 2; hh++) {
                int r = mt * 16 + hh * 8 + g;
#pragma unroll
                for (int nt = 0; nt < 4; nt++) {
                    *reinterpret_cast<float2*>(&red[msl][r][nt * 8 + 2 * t4]) =
                        make_float2(acc[mt][nt][hh * 2 + 0], acc[mt][nt][hh * 2 + 1]);
                }
            }
    }
    __syncthreads();

    if (dh == 0) {
#pragma unroll
        for (int mt = 0; mt < 2; mt++) {
#pragma unroll
            for (int hh = 0; hh < 2; hh++) {
                int r = mt * 16 + hh * 8 + g;
                int m = bm0 + msl * 32 + r;
#pragma unroll
                for (int nt = 0; nt < 4; nt++) {
                    float2 o = *reinterpret_cast<const float2*>(&red[msl][r][nt * 8 + 2 * t4]);
                    float S0 = acc[mt][nt][hh * 2 + 0] + o.x;
                    float S1 = acc[mt][nt][hh * 2 + 1] + o.y;
                    float y0 = 1.0f / (1.0f + S0);
                    float y1 = 1.0f / (1.0f + S1);
                    if (z) { y0 = 1.0f - y0; y1 = 1.0f - y1; }
                    int col = bn0 + nt * 8 + 2 * t4;
                    *reinterpret_cast<float2*>(&out[m * NOUT + z * NCOLS + col]) =
                        make_float2(y0, y1);
                }
            }
        }
    }
}

extern "C" void kernel_launch(void* const* d_in, const int* in_sizes, int n_in,
                              void* d_out, int out_size)
{
    const float* x    = (const float*)d_in[0];
    const float* Wcon = (const float*)d_in[1];
    const float* Wdis = (const float*)d_in[2];
    float* out = (float*)d_out;

    prep_kernel<<<384, 256>>>(x, Wcon, Wdis);   // 98304 threads

    dim3 grid(NCOLS / NTILE, 1024 / MTILE, 2);  // (8, 8, 2) = 128 CTAs
    union_mma_kernel<<<grid, THREADS>>>(out);
}